// round 15
// baseline (speedup 1.0000x reference)
#include <cuda_runtime.h>
#include <math.h>

#define BDIM 256            // 128 angles x 2 edge-halves
#define NPTS 64
#define HALF_PTS 32
#define PI_F      3.14159265358979f
#define INV_PI_F  0.318309886183791f
#define MAGIC_F   12582912.0f
#define EPS_U     3.1830989e-5f   // 1e-4 / pi

__device__ __forceinline__ float rcp_approx(float x) {
    float r; asm("rcp.approx.f32 %0, %1;" : "=f"(r) : "f"(x)); return r;
}

__global__ __launch_bounds__(BDIM)
void scatter_polygon_kernel(const float* __restrict__ points,
                            const float* __restrict__ phi,
                            float* __restrict__ out,
                            int B, int N) {
    // Two batches staged per block (two points per float4).
    __shared__ float4 spA[NPTS / 2];
    __shared__ float4 spB[NPTS / 2];

    const int bpair = blockIdx.y;
    const int b0 = 2 * bpair;
    const int b1 = b0 + 1;

    const int tid = threadIdx.x;
    const int alocal = tid >> 1;            // angle within block (0..127)
    const int h = tid & 1;                  // edge-half (0: pts 0-31, 1: 32-63)
    const int n = blockIdx.x * (BDIM / 2) + alocal;

    // Stage 256 floats with 256 threads (1 each).
    {
        const float* src = points + b0 * 2 * NPTS;
        if (tid < 2 * NPTS)
            reinterpret_cast<float*>(spA)[tid] = src[tid];
        else
            reinterpret_cast<float*>(spB)[tid - 2 * NPTS] = src[tid];
    }
    __syncthreads();

    if (n >= N) return;     // N multiple of 128 -> uniform per warp

    // Per-angle constants — accurate libm sincos (phi ~ pi/2 -> |q| tiny,
    // scale ~ 1/delta^2; needs exact reduction). Computed by both half-threads
    // but amortized over two batches.
    float sphi, cphi;
    sincosf(phi[n], &sphi, &cphi);
    const float qx = cphi;
    const float qy = sphi - 1.0f;
    const float scale = 1.0f / fabsf(qx * qx + qy * qy);
    const float qxp = qx * INV_PI_F;
    const float qyp = qy * INV_PI_F;
    const float nqyp = -qyp;

    // Scalar eval: u = (p.q)/pi, hc = (p.q_cross)/pi, (s,c) = sincos(p.q)
    // via mod-pi reduction; Chebyshev-economized sin(pi f) deg-7 /
    // cos(pi f) deg-8 on [-1/2,1/2] (smooth err <= ~4e-6; leading terms
    // exact -> relative accuracy for small args).
    auto eval1 = [&](float px, float py,
                     float& u, float& hc, float& s, float& c) {
        u  = fmaf(px, qxp, py * qyp);
        hc = fmaf(py, qxp, px * nqyp);
        const float t  = u + MAGIC_F;
        const float nf = t - MAGIC_F;         // round(u)
        const float f  = u - nf;              // exact (Sterbenz)
        const float f2 = f * f;

        float w = fmaf(f2, -0.55305645f, 2.54150018f);
        w = fmaf(f2, w, -5.16711112f);
        w = fmaf(f2, w, 3.14158137f);
        const float sp = f * w;               // sin(pi f)

        float v = fmaf(f2, 0.21920132f, -1.33173449f);
        v = fmaf(f2, v, 4.05839710f);
        v = fmaf(f2, v, -4.93479236f);
        const float cp = fmaf(f2, v, 1.0f);   // cos(pi f)

        const int g = __float_as_int(t) << 31;   // (-1)^n sign bit
        s = __int_as_float(__float_as_int(sp) ^ g);
        c = __int_as_float(__float_as_int(cp) ^ g);
    };

    // Per-batch running state; this thread covers edges [h*32, h*32+32),
    // prev point = h*32 - 1 mod 64 (odd index -> .zw slot).
    const int pprev = (h * HALF_PTS + NPTS - 1) & (NPTS - 1);   // 63 or 31
    float upA, hpA, spvA, cpvA, upB, hpB, spvB, cpvB;
    {
        const float4 plA = spA[pprev >> 1];
        const float4 plB = spB[pprev >> 1];
        eval1(plA.z, plA.w, upA, hpA, spvA, cpvA);
        eval1(plB.z, plB.w, upB, hpB, spvB, cpvB);
    }

    float sum_rA = 0.0f, nsum_iA = 0.0f;      // nsum accumulates -imag
    float sum_rB = 0.0f, nsum_iB = 0.0f;

    auto edgeA = [&](float uc, float hc, float sc, float cc) {
        const float du = uc - upA;
        const float dc = hc - hpA;
        const float rin = rcp_approx(du);
        const bool big = fabsf(du) >= EPS_U;
        const float m  = big ? rin : PI_F;
        const float f  = dc * m;
        const float vr = big ? (cpvA - cc) : spvA;
        const float vi = big ? (sc - spvA) : cpvA;
        sum_rA  = fmaf(f, vr, sum_rA);
        nsum_iA = fmaf(f, vi, nsum_iA);
        upA = uc; hpA = hc; spvA = sc; cpvA = cc;
    };
    auto edgeB = [&](float uc, float hc, float sc, float cc) {
        const float du = uc - upB;
        const float dc = hc - hpB;
        const float rin = rcp_approx(du);
        const bool big = fabsf(du) >= EPS_U;
        const float m  = big ? rin : PI_F;
        const float f  = dc * m;
        const float vr = big ? (cpvB - cc) : spvB;
        const float vi = big ? (sc - spvB) : cpvB;
        sum_rB  = fmaf(f, vr, sum_rB);
        nsum_iB = fmaf(f, vi, nsum_iB);
        upB = uc; hpB = hc; spvB = sc; cpvB = cc;
    };

    const int kk0 = h * (HALF_PTS / 2);       // float4 start index for my half
#pragma unroll 8
    for (int kk = 0; kk < HALF_PTS / 2; ++kk) {
        const float4 pa = spA[kk0 + kk];
        const float4 pb = spB[kk0 + kk];
        float u0, h0, s0, c0, u1, h1, s1, c1;
        float u2, h2, s2, c2, u3, h3, s3, c3;
        // Four independent eval chains (2 points x 2 batches) -> ILP 4.
        eval1(pa.x, pa.y, u0, h0, s0, c0);
        eval1(pb.x, pb.y, u2, h2, s2, c2);
        eval1(pa.z, pa.w, u1, h1, s1, c1);
        eval1(pb.z, pb.w, u3, h3, s3, c3);
        edgeA(u0, h0, s0, c0);
        edgeB(u2, h2, s2, c2);
        edgeA(u1, h1, s1, c1);
        edgeB(u3, h3, s3, c3);
    }

    // Combine edge-halves (pair = lanes 2t, 2t+1 of the same warp).
    sum_rA  += __shfl_xor_sync(0xFFFFFFFF, sum_rA, 1);
    nsum_iA += __shfl_xor_sync(0xFFFFFFFF, nsum_iA, 1);
    sum_rB  += __shfl_xor_sync(0xFFFFFFFF, sum_rB, 1);
    nsum_iB += __shfl_xor_sync(0xFFFFFFFF, nsum_iB, 1);

    if (h == 0) {
        out[(b0 * 2 + 0) * N + n] = scale * sum_rA;
        out[(b0 * 2 + 1) * N + n] = -(scale * nsum_iA);
        out[(b1 * 2 + 0) * N + n] = scale * sum_rB;
        out[(b1 * 2 + 1) * N + n] = -(scale * nsum_iB);
    }
}

extern "C" void kernel_launch(void* const* d_in, const int* in_sizes, int n_in,
                              void* d_out, int out_size) {
    const float* points = (const float*)d_in[0];  // [B, 64, 2] f32
    const float* phi    = (const float*)d_in[1];  // [N] f32
    float* out = (float*)d_out;                   // [B, 2, N] f32

    const int N = in_sizes[1];
    const int B = in_sizes[0] / (2 * NPTS);

    const int angles_per_block = BDIM / 2;
    dim3 grid((N + angles_per_block - 1) / angles_per_block, B / 2);
    scatter_polygon_kernel<<<grid, BDIM>>>(points, phi, out, B, N);
}

// round 16
// speedup vs baseline: 1.0026x; 1.0026x over previous
#include <cuda_runtime.h>
#include <math.h>

#define BDIM 128
#define NPTS 64
#define PI_F      3.14159265358979f
#define INV_PI_F  0.318309886183791f
#define MAGIC_F   12582912.0f
#define EPS_U     3.1830989e-5f   // 1e-4 / pi

__device__ __forceinline__ float rcp_approx(float x) {
    float r; asm("rcp.approx.f32 %0, %1;" : "=f"(r) : "f"(x)); return r;
}

// 16 blocks/SM x 128 threads x 32 regs = 64K regs: forces <=32 regs so the
// whole 2048-block grid is resident in ONE wave (no second-wave tail).
__global__ __launch_bounds__(BDIM, 16)
void scatter_polygon_kernel(const float* __restrict__ points,
                            const float* __restrict__ phi,
                            float* __restrict__ out,
                            int B, int N) {
    __shared__ float4 spts[NPTS / 2];   // two points per float4

    const int b = blockIdx.y;
    const int n = blockIdx.x * BDIM + threadIdx.x;

    reinterpret_cast<float*>(spts)[threadIdx.x] = points[b * 2 * NPTS + threadIdx.x];
    __syncthreads();

    if (n >= N) return;

    // Per-angle constants — accurate libm sincos (phi ~ pi/2 -> |q| tiny,
    // scale ~ 1/delta^2 huge; q needs ~1e-7 absolute accuracy).
    float sphi, cphi;
    sincosf(phi[n], &sphi, &cphi);
    const float qx = cphi;
    const float qy = sphi - 1.0f;
    const float scale = 1.0f / fabsf(qx * qx + qy * qy);
    const float qxp = qx * INV_PI_F;
    const float qyp = qy * INV_PI_F;
    const float nqyp = -qyp;

    // Scalar eval: u = (p.q)/pi, hc = (p.q_cross)/pi, (s,c) = sincos(p.q)
    // via mod-pi reduction; Chebyshev-economized sin(pi f) deg-7 /
    // cos(pi f) deg-8 on [-1/2,1/2]. Smooth error <= ~4e-6; leading terms
    // exact -> relative accuracy preserved for small arguments.
    auto eval1 = [&](float px, float py,
                     float& u, float& hc, float& s, float& c) {
        u  = fmaf(px, qxp, py * qyp);
        hc = fmaf(py, qxp, px * nqyp);
        const float t  = u + MAGIC_F;
        const float nf = t - MAGIC_F;         // round(u)
        const float f  = u - nf;              // exact (Sterbenz)
        const float f2 = f * f;

        float w = fmaf(f2, -0.55305645f, 2.54150018f);
        w = fmaf(f2, w, -5.16711112f);
        w = fmaf(f2, w, 3.14158137f);
        const float sp = f * w;               // sin(pi f), econ deg 7

        float v = fmaf(f2, 0.21920132f, -1.33173449f);
        v = fmaf(f2, v, 4.05839710f);
        v = fmaf(f2, v, -4.93479236f);
        const float cp = fmaf(f2, v, 1.0f);   // cos(pi f), econ deg 8

        const int g = __float_as_int(t) << 31;   // (-1)^n sign bit
        s = __int_as_float(__float_as_int(sp) ^ g);
        c = __int_as_float(__float_as_int(cp) ^ g);
    };

    float sum_r = 0.0f, nsum_i = 0.0f;        // nsum_i accumulates -imag

    // prev = point[NPTS-1]
    float up, hp, sprev, cprev;
    {
        const float4 pl = spts[NPTS / 2 - 1];
        eval1(pl.z, pl.w, up, hp, sprev, cprev);
    }

    // edge (prev -> cur). One select chooses the multiplier:
    //  case1 (|ddq|>=eps): f = dc*rcp(du);  r += f*(cprev-cc), -i += f*(sc-sprev)
    //  case2:              f = dc*pi;       r += f*sprev,      -i += f*cprev
    auto edge = [&](float uc, float hc, float sc, float cc) {
        const float du = uc - up;             // ddq / pi
        const float dc = hc - hp;             // ddqc / pi
        const float rin = rcp_approx(du);
        const bool big = fabsf(du) >= EPS_U;
        const float m  = big ? rin : PI_F;
        const float f  = dc * m;
        const float vr = big ? (cprev - cc) : sprev;
        const float vi = big ? (sc - sprev) : cprev;
        sum_r  = fmaf(f, vr, sum_r);
        nsum_i = fmaf(f, vi, nsum_i);
        up = uc; hp = hc; sprev = sc; cprev = cc;
    };

#pragma unroll 8
    for (int kk = 0; kk < NPTS / 2; ++kk) {   // unroll 8: fits 32 regs (r9)
        const float4 pc = spts[kk];           // points 2kk (x,y), 2kk+1 (z,w)
        float u0, h0, s0, c0, u1, h1, s1, c1;
        eval1(pc.x, pc.y, u0, h0, s0, c0);    // two independent scalar chains
        eval1(pc.z, pc.w, u1, h1, s1, c1);
        edge(u0, h0, s0, c0);
        edge(u1, h1, s1, c1);
    }

    out[(b * 2 + 0) * N + n] = scale * sum_r;
    out[(b * 2 + 1) * N + n] = -(scale * nsum_i);
}

extern "C" void kernel_launch(void* const* d_in, const int* in_sizes, int n_in,
                              void* d_out, int out_size) {
    const float* points = (const float*)d_in[0];  // [B, 64, 2] f32
    const float* phi    = (const float*)d_in[1];  // [N] f32
    float* out = (float*)d_out;                   // [B, 2, N] f32

    const int N = in_sizes[1];
    const int B = in_sizes[0] / (2 * NPTS);

    dim3 grid((N + BDIM - 1) / BDIM, B);
    scatter_polygon_kernel<<<grid, BDIM>>>(points, phi, out, B, N);
}